// round 1
// baseline (speedup 1.0000x reference)
#include <cuda_runtime.h>
#include <cuda_bf16.h>

// ---------------------------------------------------------------------------
// JKNet: 3x GraphConv (norm='both') + JK-cat + final adjacency sum + linear.
//
// Key algebra: segment_sum is linear =>
//   agg((x*srcn)@W) == agg(x*srcn)@W      (aggregate first, GEMM second)
//   hagg@Wout       == sum_l segsum(h_l[src]) @ Wout_slice_l
// Layer-(l+1) scaled agg and final-slice-l plain agg of h_l share gathers ->
// fused dual-accumulator aggregation pass.
// ---------------------------------------------------------------------------

#define NN 50000
#define EE 800000
#define DD 128

// ---------------- scratch (device globals; no allocation allowed) ----------
__device__ float g_h0[NN * DD];
__device__ float g_h1[NN * DD];
__device__ float g_A [NN * DD];   // aggregated (scaled) input for next GEMM
__device__ float g_F [NN * DD];   // aggregated (plain) for output GEMM
__device__ float g_srcn[NN];
__device__ float g_dstn[NN];
__device__ int   g_outdeg[NN];
__device__ int   g_indeg [NN];
__device__ int   g_rowptr[NN + 1];
__device__ int   g_cursor[NN];
__device__ int   g_colidx[EE];
__device__ int   g_bsum[256];

// ---------------- CSR build ------------------------------------------------
__global__ void zero_ints(int* __restrict__ a, int* __restrict__ b, int n) {
    int i = blockIdx.x * blockDim.x + threadIdx.x;
    if (i < n) { a[i] = 0; b[i] = 0; }
}

__global__ void deg_hist(const int* __restrict__ src, const int* __restrict__ dst,
                         int* __restrict__ outdeg, int* __restrict__ indeg, int e) {
    int i = blockIdx.x * blockDim.x + threadIdx.x;
    if (i < e) {
        atomicAdd(&outdeg[src[i]], 1);
        atomicAdd(&indeg [dst[i]], 1);
    }
}

__global__ void norms_kernel(const int* __restrict__ outdeg, const int* __restrict__ indeg,
                             float* __restrict__ sn, float* __restrict__ dn, int n) {
    int i = blockIdx.x * blockDim.x + threadIdx.x;
    if (i < n) {
        sn[i] = rsqrtf((float)max(outdeg[i], 1));
        dn[i] = rsqrtf((float)max(indeg [i], 1));
    }
}

__global__ void scan_block_sums(const int* __restrict__ deg, int* __restrict__ bsum, int n) {
    __shared__ int s[256];
    int i = blockIdx.x * 256 + threadIdx.x;
    s[threadIdx.x] = (i < n) ? deg[i] : 0;
    __syncthreads();
    for (int off = 128; off > 0; off >>= 1) {
        if (threadIdx.x < off) s[threadIdx.x] += s[threadIdx.x + off];
        __syncthreads();
    }
    if (threadIdx.x == 0) bsum[blockIdx.x] = s[0];
}

// single block, nb <= 256: exclusive scan of block sums in-place
__global__ void scan_bsums(int* __restrict__ bsum, int nb) {
    __shared__ int s[256];
    int t = threadIdx.x;
    int v = (t < nb) ? bsum[t] : 0;
    s[t] = v;
    __syncthreads();
    for (int off = 1; off < 256; off <<= 1) {
        int add = (t >= off) ? s[t - off] : 0;
        __syncthreads();
        s[t] += add;
        __syncthreads();
    }
    if (t < nb) bsum[t] = s[t] - v;   // exclusive
}

__global__ void scan_final(const int* __restrict__ deg, const int* __restrict__ bsum,
                           int* __restrict__ rowptr, int* __restrict__ cursor,
                           int n, int etot) {
    __shared__ int s[256];
    int t = threadIdx.x;
    int i = blockIdx.x * 256 + t;
    int v = (i < n) ? deg[i] : 0;
    s[t] = v;
    __syncthreads();
    for (int off = 1; off < 256; off <<= 1) {
        int add = (t >= off) ? s[t - off] : 0;
        __syncthreads();
        s[t] += add;
        __syncthreads();
    }
    int ex = bsum[blockIdx.x] + s[t] - v;
    if (i < n) { rowptr[i] = ex; cursor[i] = ex; }
    if (i == 0) rowptr[n] = etot;
}

__global__ void scatter_edges(const int* __restrict__ src, const int* __restrict__ dst,
                              int* __restrict__ cursor, int* __restrict__ colidx, int e) {
    int i = blockIdx.x * blockDim.x + threadIdx.x;
    if (i < e) {
        int p = atomicAdd(&cursor[dst[i]], 1);
        colidx[p] = src[i];
    }
}

// ---------------- sparse aggregation (gather, warp per node) ---------------
// MODE 0: scaled only     outS = sum srcn[s]*X[s]
// MODE 1: dual            outS = scaled sum, outP = plain sum
// MODE 2: plain only      outP = sum X[s]
template <int MODE>
__global__ void agg_kernel(const float* __restrict__ X,
                           const int* __restrict__ rowptr,
                           const int* __restrict__ colidx,
                           const float* __restrict__ srcn,
                           float* __restrict__ outS,
                           float* __restrict__ outP, int n) {
    int warp = (blockIdx.x * blockDim.x + threadIdx.x) >> 5;
    int lane = threadIdx.x & 31;
    if (warp >= n) return;
    int beg = rowptr[warp];
    int end = rowptr[warp + 1];
    const float4* __restrict__ X4 = (const float4*)X;

    float4 aS = make_float4(0.f, 0.f, 0.f, 0.f);
    float4 aP = make_float4(0.f, 0.f, 0.f, 0.f);

    int e = beg;
    for (; e + 1 < end; e += 2) {
        int s0 = colidx[e];
        int s1 = colidx[e + 1];
        float4 v0 = X4[s0 * 32 + lane];
        float4 v1 = X4[s1 * 32 + lane];
        if (MODE != 2) {
            float n0 = srcn[s0], n1 = srcn[s1];
            aS.x += v0.x * n0 + v1.x * n1;
            aS.y += v0.y * n0 + v1.y * n1;
            aS.z += v0.z * n0 + v1.z * n1;
            aS.w += v0.w * n0 + v1.w * n1;
        }
        if (MODE != 0) {
            aP.x += v0.x + v1.x;
            aP.y += v0.y + v1.y;
            aP.z += v0.z + v1.z;
            aP.w += v0.w + v1.w;
        }
    }
    if (e < end) {
        int s0 = colidx[e];
        float4 v0 = X4[s0 * 32 + lane];
        if (MODE != 2) {
            float n0 = srcn[s0];
            aS.x += v0.x * n0; aS.y += v0.y * n0;
            aS.z += v0.z * n0; aS.w += v0.w * n0;
        }
        if (MODE != 0) {
            aP.x += v0.x; aP.y += v0.y; aP.z += v0.z; aP.w += v0.w;
        }
    }
    if (MODE != 2) ((float4*)outS)[warp * 32 + lane] = aS;
    if (MODE != 0) ((float4*)outP)[warp * 32 + lane] = aP;
}

// ---------------- dense GEMM [n,128] @ [128,128] ---------------------------
// MODE 0: C = relu(acc * dstn[row] + bias[col])
// MODE 1: C = acc + bias[col]           (first output slice)
// MODE 2: C = C + acc                   (accumulate output slice)
#define GR 32   // rows per block
#define KT 64   // k tile
template <int MODE>
__global__ void gemm128(const float* __restrict__ A, const float* __restrict__ W,
                        const float* __restrict__ bias, const float* __restrict__ dstn,
                        float* __restrict__ C, int n) {
    __shared__ float sW[KT * 128];   // 32 KB
    __shared__ float sA[GR * KT];    // 8 KB
    int tid  = threadIdx.x;          // 256 threads = 8 warps
    int lane = tid & 31;
    int warp = tid >> 5;
    int row0 = blockIdx.x * GR;

    float4 acc[4];
#pragma unroll
    for (int r = 0; r < 4; r++) acc[r] = make_float4(0.f, 0.f, 0.f, 0.f);

    for (int k0 = 0; k0 < 128; k0 += KT) {
        __syncthreads();
        // W tile: KT x 128 = 2048 float4, 8 per thread, coalesced
        const float4* Wg  = (const float4*)(W + k0 * 128);
        float4*       sW4 = (float4*)sW;
#pragma unroll
        for (int i = 0; i < 8; i++) sW4[i * 256 + tid] = Wg[i * 256 + tid];
        // A tile: GR x KT = 512 float4, 2 per thread
#pragma unroll
        for (int i = 0; i < 2; i++) {
            int idx = i * 256 + tid;       // 0..511
            int r   = idx >> 4;            // KT/4 = 16 float4 per row
            int c4  = idx & 15;
            float4 v = make_float4(0.f, 0.f, 0.f, 0.f);
            if (row0 + r < n)
                v = ((const float4*)(A + (row0 + r) * 128 + k0))[c4];
            ((float4*)sA)[idx] = v;
        }
        __syncthreads();
#pragma unroll
        for (int k = 0; k < KT; k++) {
            float4 w = ((float4*)sW)[k * 32 + lane];
#pragma unroll
            for (int r = 0; r < 4; r++) {
                float a = sA[(warp * 4 + r) * KT + k];
                acc[r].x += a * w.x;
                acc[r].y += a * w.y;
                acc[r].z += a * w.z;
                acc[r].w += a * w.w;
            }
        }
    }

    float4 bv = make_float4(0.f, 0.f, 0.f, 0.f);
    if (MODE != 2) bv = ((const float4*)bias)[lane];

#pragma unroll
    for (int r = 0; r < 4; r++) {
        int row = row0 + warp * 4 + r;
        if (row >= n) continue;
        float4 v = acc[r];
        if (MODE == 0) {
            float dn = dstn[row];
            v.x = fmaxf(fmaf(v.x, dn, bv.x), 0.f);
            v.y = fmaxf(fmaf(v.y, dn, bv.y), 0.f);
            v.z = fmaxf(fmaf(v.z, dn, bv.z), 0.f);
            v.w = fmaxf(fmaf(v.w, dn, bv.w), 0.f);
        } else if (MODE == 1) {
            v.x += bv.x; v.y += bv.y; v.z += bv.z; v.w += bv.w;
        } else {
            float4 old = ((const float4*)C)[row * 32 + lane];
            v.x += old.x; v.y += old.y; v.z += old.z; v.w += old.w;
        }
        ((float4*)C)[row * 32 + lane] = v;
    }
}

// ---------------------------------------------------------------------------
extern "C" void kernel_launch(void* const* d_in, const int* in_sizes, int n_in,
                              void* d_out, int out_size) {
    const float* feats = (const float*)d_in[0];
    const int*   src   = (const int*)  d_in[1];
    const int*   dst   = (const int*)  d_in[2];
    const float* W0    = (const float*)d_in[3];
    const float* b0    = (const float*)d_in[4];
    const float* W1    = (const float*)d_in[5];
    const float* b1    = (const float*)d_in[6];
    const float* W2    = (const float*)d_in[7];
    const float* b2    = (const float*)d_in[8];
    const float* Wout  = (const float*)d_in[9];
    const float* bout  = (const float*)d_in[10];
    float*       out   = (float*)d_out;

    const int n = in_sizes[0] / DD;   // 50000
    const int e = in_sizes[1];        // 800000

    float *A, *F, *h0, *h1, *srcn, *dstn;
    int *outdeg, *indeg, *rowptr, *cursor, *colidx, *bsum;
    cudaGetSymbolAddress((void**)&A,      g_A);
    cudaGetSymbolAddress((void**)&F,      g_F);
    cudaGetSymbolAddress((void**)&h0,     g_h0);
    cudaGetSymbolAddress((void**)&h1,     g_h1);
    cudaGetSymbolAddress((void**)&srcn,   g_srcn);
    cudaGetSymbolAddress((void**)&dstn,   g_dstn);
    cudaGetSymbolAddress((void**)&outdeg, g_outdeg);
    cudaGetSymbolAddress((void**)&indeg,  g_indeg);
    cudaGetSymbolAddress((void**)&rowptr, g_rowptr);
    cudaGetSymbolAddress((void**)&cursor, g_cursor);
    cudaGetSymbolAddress((void**)&colidx, g_colidx);
    cudaGetSymbolAddress((void**)&bsum,   g_bsum);

    const int nbN  = (n + 255) / 256;       // 196
    const int nbE  = (e + 255) / 256;       // 3125
    const int nbAg = (n + 7) / 8;           // warp per node, 8 warps/block
    const int nbGm = (n + GR - 1) / GR;     // 1563

    // ---- CSR build + norms ----
    zero_ints      <<<nbN, 256>>>(outdeg, indeg, n);
    deg_hist       <<<nbE, 256>>>(src, dst, outdeg, indeg, e);
    scan_block_sums<<<nbN, 256>>>(indeg, bsum, n);
    scan_bsums     <<<1,   256>>>(bsum, nbN);
    scan_final     <<<nbN, 256>>>(indeg, bsum, rowptr, cursor, n, e);
    norms_kernel   <<<nbN, 256>>>(outdeg, indeg, srcn, dstn, n);
    scatter_edges  <<<nbE, 256>>>(src, dst, cursor, colidx, e);

    // ---- layer 1: A = agg_scaled(feats); h0 = relu(A@W0 * dstn + b0) ----
    agg_kernel<0><<<nbAg, 256>>>(feats, rowptr, colidx, srcn, A, nullptr, n);
    gemm128<0>   <<<nbGm, 256>>>(A, W0, b0, dstn, h0, n);

    // ---- layer 2 + out slice 0 (dual agg of h0) ----
    agg_kernel<1><<<nbAg, 256>>>(h0, rowptr, colidx, srcn, A, F, n);
    gemm128<0>   <<<nbGm, 256>>>(A, W1, b1, dstn, h1, n);
    gemm128<1>   <<<nbGm, 256>>>(F, Wout + 0 * DD * DD, bout, nullptr, out, n);

    // ---- layer 3 + out slice 1 (dual agg of h1) ----
    agg_kernel<1><<<nbAg, 256>>>(h1, rowptr, colidx, srcn, A, F, n);
    gemm128<0>   <<<nbGm, 256>>>(A, W2, b2, dstn, h0, n);  // reuse h0 as h2
    gemm128<2>   <<<nbGm, 256>>>(F, Wout + 1 * DD * DD, nullptr, nullptr, out, n);

    // ---- out slice 2 (plain agg of h2) ----
    agg_kernel<2><<<nbAg, 256>>>(h0, rowptr, colidx, srcn, nullptr, F, n);
    gemm128<2>   <<<nbGm, 256>>>(F, Wout + 2 * DD * DD, nullptr, nullptr, out, n);
}

// round 6
// speedup vs baseline: 1.0758x; 1.0758x over previous
#include <cuda_runtime.h>
#include <cuda_bf16.h>
#include <mma.h>
#include <cstdint>

using namespace nvcuda;

// ---------------------------------------------------------------------------
// JKNet: 3x GraphConv (norm='both') + JK-cat + final adjacency sum + linear.
// R6: tensor cores via nvcuda::wmma (NO inline PTX anywhere). bf16 hi/lo
//     3-pass split GEMM (~fp32 accuracy). dstn folded into A, bias preloaded
//     into accumulators, relu elementwise on fragments -> direct global store.
//     Static smem 46KB. Agg/CSR identical to the R1 kernel that passed.
// ---------------------------------------------------------------------------

#define NN 50000
#define EE 800000
#define DD 128

// ---------------- scratch ---------------------------------------------------
__device__ float g_h0[NN * DD];
__device__ float g_h1[NN * DD];
__device__ float g_A [NN * DD];
__device__ float g_F0[NN * DD];
__device__ float g_F1[NN * DD];
__device__ float g_F2[NN * DD];
__device__ float g_srcn[NN];
__device__ float g_dstn[NN];
__device__ int   g_outdeg[NN];
__device__ int   g_indeg [NN];
__device__ int   g_rowptr[NN + 1];
__device__ int   g_cursor[NN];
__device__ int   g_colidx[EE];
__device__ int   g_bsum[256];
// bf16 weight images, plain row-major [k][n] (B = W as stored), hi + lo parts
__device__ __nv_bfloat16 g_Bhi[6 * DD * DD];
__device__ __nv_bfloat16 g_Blo[6 * DD * DD];

// ---------------- CSR build -------------------------------------------------
__global__ void zero_ints(int* __restrict__ a, int* __restrict__ b, int n) {
    int i = blockIdx.x * blockDim.x + threadIdx.x;
    if (i < n) { a[i] = 0; b[i] = 0; }
}
__global__ void deg_hist(const int* __restrict__ src, const int* __restrict__ dst,
                         int* __restrict__ outdeg, int* __restrict__ indeg, int e) {
    int i = blockIdx.x * blockDim.x + threadIdx.x;
    if (i < e) { atomicAdd(&outdeg[src[i]], 1); atomicAdd(&indeg[dst[i]], 1); }
}
__global__ void norms_kernel(const int* __restrict__ outdeg, const int* __restrict__ indeg,
                             float* __restrict__ sn, float* __restrict__ dn, int n) {
    int i = blockIdx.x * blockDim.x + threadIdx.x;
    if (i < n) {
        sn[i] = rsqrtf((float)max(outdeg[i], 1));
        dn[i] = rsqrtf((float)max(indeg [i], 1));
    }
}
__global__ void scan_block_sums(const int* __restrict__ deg, int* __restrict__ bsum, int n) {
    __shared__ int s[256];
    int i = blockIdx.x * 256 + threadIdx.x;
    s[threadIdx.x] = (i < n) ? deg[i] : 0;
    __syncthreads();
    for (int off = 128; off > 0; off >>= 1) {
        if (threadIdx.x < off) s[threadIdx.x] += s[threadIdx.x + off];
        __syncthreads();
    }
    if (threadIdx.x == 0) bsum[blockIdx.x] = s[0];
}
__global__ void scan_bsums(int* __restrict__ bsum, int nb) {
    __shared__ int s[256];
    int t = threadIdx.x;
    int v = (t < nb) ? bsum[t] : 0;
    s[t] = v;
    __syncthreads();
    for (int off = 1; off < 256; off <<= 1) {
        int add = (t >= off) ? s[t - off] : 0;
        __syncthreads();
        s[t] += add;
        __syncthreads();
    }
    if (t < nb) bsum[t] = s[t] - v;
}
__global__ void scan_final(const int* __restrict__ deg, const int* __restrict__ bsum,
                           int* __restrict__ rowptr, int* __restrict__ cursor,
                           int n, int etot) {
    __shared__ int s[256];
    int t = threadIdx.x;
    int i = blockIdx.x * 256 + t;
    int v = (i < n) ? deg[i] : 0;
    s[t] = v;
    __syncthreads();
    for (int off = 1; off < 256; off <<= 1) {
        int add = (t >= off) ? s[t - off] : 0;
        __syncthreads();
        s[t] += add;
        __syncthreads();
    }
    int ex = bsum[blockIdx.x] + s[t] - v;
    if (i < n) { rowptr[i] = ex; cursor[i] = ex; }
    if (i == 0) rowptr[n] = etot;
}
__global__ void scatter_edges(const int* __restrict__ src, const int* __restrict__ dst,
                              int* __restrict__ cursor, int* __restrict__ colidx, int e) {
    int i = blockIdx.x * blockDim.x + threadIdx.x;
    if (i < e) {
        int p = atomicAdd(&cursor[dst[i]], 1);
        colidx[p] = src[i];
    }
}

// ---------------- W conversion: fp32 -> bf16 hi/lo, row-major [k][n] --------
__global__ void conv_w(const float* __restrict__ W0, const float* __restrict__ W1,
                       const float* __restrict__ W2, const float* __restrict__ Wout,
                       __nv_bfloat16* __restrict__ hi, __nv_bfloat16* __restrict__ lo) {
    int idx = blockIdx.x * blockDim.x + threadIdx.x;
    if (idx >= 6 * DD * DD) return;
    int m = idx / (DD * DD);
    int rem = idx % (DD * DD);
    const float* src = (m == 0) ? W0 : (m == 1) ? W1 : (m == 2) ? W2
                                     : (Wout + (m - 3) * DD * DD);
    float v = src[rem];
    __nv_bfloat16 h = __float2bfloat16(v);
    __nv_bfloat16 l = __float2bfloat16(v - __bfloat162float(h));
    hi[idx] = h;
    lo[idx] = l;
}

// ---------------- sparse aggregation (gather, warp per node) ----------------
template <int MODE>   // 0 scaled, 1 dual, 2 plain
__global__ void agg_kernel(const float* __restrict__ X,
                           const int* __restrict__ rowptr,
                           const int* __restrict__ colidx,
                           const float* __restrict__ srcn,
                           float* __restrict__ outS,
                           float* __restrict__ outP, int n) {
    int warp = (blockIdx.x * blockDim.x + threadIdx.x) >> 5;
    int lane = threadIdx.x & 31;
    if (warp >= n) return;
    int beg = rowptr[warp];
    int end = rowptr[warp + 1];
    const float4* __restrict__ X4 = (const float4*)X;

    float4 aS = make_float4(0.f, 0.f, 0.f, 0.f);
    float4 aP = make_float4(0.f, 0.f, 0.f, 0.f);
    int e = beg;
    for (; e + 1 < end; e += 2) {
        int s0 = colidx[e], s1 = colidx[e + 1];
        float4 v0 = X4[s0 * 32 + lane];
        float4 v1 = X4[s1 * 32 + lane];
        if (MODE != 2) {
            float n0 = srcn[s0], n1 = srcn[s1];
            aS.x += v0.x * n0 + v1.x * n1;  aS.y += v0.y * n0 + v1.y * n1;
            aS.z += v0.z * n0 + v1.z * n1;  aS.w += v0.w * n0 + v1.w * n1;
        }
        if (MODE != 0) {
            aP.x += v0.x + v1.x;  aP.y += v0.y + v1.y;
            aP.z += v0.z + v1.z;  aP.w += v0.w + v1.w;
        }
    }
    if (e < end) {
        int s0 = colidx[e];
        float4 v0 = X4[s0 * 32 + lane];
        if (MODE != 2) {
            float n0 = srcn[s0];
            aS.x += v0.x * n0; aS.y += v0.y * n0; aS.z += v0.z * n0; aS.w += v0.w * n0;
        }
        if (MODE != 0) { aP.x += v0.x; aP.y += v0.y; aP.z += v0.z; aP.w += v0.w; }
    }
    if (MODE != 2) ((float4*)outS)[warp * 32 + lane] = aS;
    if (MODE != 0) ((float4*)outP)[warp * 32 + lane] = aP;
}

// ---------------- WMMA GEMM [n,128*NSEG] @ [128*NSEG,128] -------------------
// Per block: 128x128 C tile, 8 warps (warp w -> rows w*16..w*16+15, all cols).
// K processed in 32-wide slices. A staged as (A*dn) bf16 hi/lo [128][40],
// B staged bf16 hi/lo [32][136]. 3-pass split: AhBh + AhBl + AlBh.
// MODE 0: C = relu((A*dn)@W + bias);  MODE 1: C = A@W + bias.
#define ALD 40     // A smem leading dim (elems)
#define BLD 136    // B smem leading dim (elems)

template <int MODE, int NSEG>
__global__ void __launch_bounds__(256)
mma_gemm(const float* __restrict__ A0, const float* __restrict__ A1,
         const float* __restrict__ A2,
         const __nv_bfloat16* __restrict__ B0h, const __nv_bfloat16* __restrict__ B0l,
         const __nv_bfloat16* __restrict__ B1h, const __nv_bfloat16* __restrict__ B1l,
         const __nv_bfloat16* __restrict__ B2h, const __nv_bfloat16* __restrict__ B2l,
         const float* __restrict__ bias, const float* __restrict__ dstn,
         float* __restrict__ C, int n) {
    __shared__ __nv_bfloat16 sAhi[128 * ALD];
    __shared__ __nv_bfloat16 sAlo[128 * ALD];
    __shared__ __nv_bfloat16 sBhi[32 * BLD];
    __shared__ __nv_bfloat16 sBlo[32 * BLD];
    __shared__ float sBias[8 * 16 * 16];       // 8 col-tiles, rows replicated

    const int tid  = threadIdx.x;
    const int wid  = tid >> 5;
    const int row0 = blockIdx.x * 128;

    const float* As[3]            = {A0, A1, A2};
    const __nv_bfloat16* Bhs[3]   = {B0h, B1h, B2h};
    const __nv_bfloat16* Bls[3]   = {B0l, B1l, B2l};

    // build replicated bias tiles: sBias[nt][r][c] = bias[nt*16+c]
    for (int idx = tid; idx < 2048; idx += 256) {
        int nt = idx >> 8;
        int c  = idx & 15;
        sBias[idx] = bias[nt * 16 + c];
    }
    __syncthreads();

    wmma::fragment<wmma::accumulator, 16, 16, 16, float> acc[8];
#pragma unroll
    for (int nt = 0; nt < 8; nt++)
        wmma::load_matrix_sync(acc[nt], &sBias[nt * 256], 16, wmma::mem_row_major);

#pragma unroll
    for (int seg = 0; seg < NSEG; seg++) {
        const float* Ap = As[seg];
        const __nv_bfloat16* Bh = Bhs[seg];
        const __nv_bfloat16* Bl = Bls[seg];
#pragma unroll
        for (int ks = 0; ks < 4; ks++) {        // 32-k slices
            __syncthreads();
            // --- stage B slice: rows ks*32..+31, 128 cols, pad to BLD ---
            {
                const uint4* bh = (const uint4*)(Bh + ks * 32 * 128);
                const uint4* bl = (const uint4*)(Bl + ks * 32 * 128);
#pragma unroll
                for (int i = 0; i < 2; i++) {
                    int idx = i * 256 + tid;    // 0..511 uint4 (8 bf16 each)
                    int r   = idx >> 4;         // 16 uint4 per 128-col row
                    int c16 = idx & 15;
                    *(uint4*)(sBhi + r * BLD + c16 * 8) = bh[idx];
                    *(uint4*)(sBlo + r * BLD + c16 * 8) = bl[idx];
                }
            }
            // --- stage A slice [128 x 32] fp32 -> (A*dn) bf16 hi/lo ---
            {
#pragma unroll
                for (int i = 0; i < 4; i++) {
                    int idx4 = i * 256 + tid;   // 0..1023 float4
                    int row  = idx4 >> 3;       // 8 float4 per 32-col row
                    int c4   = idx4 & 7;
                    float4 v = make_float4(0.f, 0.f, 0.f, 0.f);
                    float dn = 1.f;
                    if (row0 + row < n) {
                        v = *(const float4*)(Ap + (size_t)(row0 + row) * 128
                                                + ks * 32 + c4 * 4);
                        if (MODE == 0) dn = dstn[row0 + row];
                    }
                    if (MODE == 0) { v.x *= dn; v.y *= dn; v.z *= dn; v.w *= dn; }
                    __nv_bfloat16 h0 = __float2bfloat16(v.x);
                    __nv_bfloat16 h1 = __float2bfloat16(v.y);
                    __nv_bfloat16 h2 = __float2bfloat16(v.z);
                    __nv_bfloat16 h3 = __float2bfloat16(v.w);
                    __nv_bfloat16 l0 = __float2bfloat16(v.x - __bfloat162float(h0));
                    __nv_bfloat16 l1 = __float2bfloat16(v.y - __bfloat162float(h1));
                    __nv_bfloat16 l2 = __float2bfloat16(v.z - __bfloat162float(h2));
                    __nv_bfloat16 l3 = __float2bfloat16(v.w - __bfloat162float(h3));
                    __nv_bfloat16* dh = sAhi + row * ALD + c4 * 4;
                    __nv_bfloat16* dl = sAlo + row * ALD + c4 * 4;
                    dh[0] = h0; dh[1] = h1; dh[2] = h2; dh[3] = h3;
                    dl[0] = l0; dl[1] = l1; dl[2] = l2; dl[3] = l3;
                }
            }
            __syncthreads();

            // --- compute: 2 k-steps of 16 ---
#pragma unroll
            for (int kk = 0; kk < 32; kk += 16) {
                wmma::fragment<wmma::matrix_a, 16, 16, 16, __nv_bfloat16, wmma::row_major> ah, al;
                wmma::load_matrix_sync(ah, sAhi + (wid * 16) * ALD + kk, ALD);
                wmma::load_matrix_sync(al, sAlo + (wid * 16) * ALD + kk, ALD);
#pragma unroll
                for (int nt = 0; nt < 8; nt++) {
                    wmma::fragment<wmma::matrix_b, 16, 16, 16, __nv_bfloat16, wmma::row_major> bh, bl;
                    wmma::load_matrix_sync(bh, sBhi + kk * BLD + nt * 16, BLD);
                    wmma::load_matrix_sync(bl, sBlo + kk * BLD + nt * 16, BLD);
                    wmma::mma_sync(acc[nt], ah, bh, acc[nt]);
                    wmma::mma_sync(acc[nt], ah, bl, acc[nt]);
                    wmma::mma_sync(acc[nt], al, bh, acc[nt]);
                }
            }
        }
    }

    // --- epilogue: optional relu (elementwise on fragment), direct store ---
    // n is a multiple of 16, so each warp's 16-row tile is all-in or all-out.
    if (row0 + wid * 16 + 16 <= n) {
#pragma unroll
        for (int nt = 0; nt < 8; nt++) {
            if (MODE == 0) {
#pragma unroll
                for (int i = 0; i < acc[nt].num_elements; i++)
                    acc[nt].x[i] = fmaxf(acc[nt].x[i], 0.f);
            }
            wmma::store_matrix_sync(C + (size_t)(row0 + wid * 16) * 128 + nt * 16,
                                    acc[nt], 128, wmma::mem_row_major);
        }
    }
}

// ---------------------------------------------------------------------------
extern "C" void kernel_launch(void* const* d_in, const int* in_sizes, int n_in,
                              void* d_out, int out_size) {
    const float* feats = (const float*)d_in[0];
    const int*   src   = (const int*)  d_in[1];
    const int*   dst   = (const int*)  d_in[2];
    const float* W0    = (const float*)d_in[3];
    const float* b0    = (const float*)d_in[4];
    const float* W1    = (const float*)d_in[5];
    const float* b1    = (const float*)d_in[6];
    const float* W2    = (const float*)d_in[7];
    const float* b2    = (const float*)d_in[8];
    const float* Wout  = (const float*)d_in[9];
    const float* bout  = (const float*)d_in[10];
    float*       out   = (float*)d_out;

    const int n = in_sizes[0] / DD;
    const int e = in_sizes[1];

    float *A, *F0, *F1, *F2, *h0, *h1, *srcn, *dstn;
    int *outdeg, *indeg, *rowptr, *cursor, *colidx, *bsum;
    __nv_bfloat16 *Bhi, *Blo;
    cudaGetSymbolAddress((void**)&A,      g_A);
    cudaGetSymbolAddress((void**)&F0,     g_F0);
    cudaGetSymbolAddress((void**)&F1,     g_F1);
    cudaGetSymbolAddress((void**)&F2,     g_F2);
    cudaGetSymbolAddress((void**)&h0,     g_h0);
    cudaGetSymbolAddress((void**)&h1,     g_h1);
    cudaGetSymbolAddress((void**)&srcn,   g_srcn);
    cudaGetSymbolAddress((void**)&dstn,   g_dstn);
    cudaGetSymbolAddress((void**)&outdeg, g_outdeg);
    cudaGetSymbolAddress((void**)&indeg,  g_indeg);
    cudaGetSymbolAddress((void**)&rowptr, g_rowptr);
    cudaGetSymbolAddress((void**)&cursor, g_cursor);
    cudaGetSymbolAddress((void**)&colidx, g_colidx);
    cudaGetSymbolAddress((void**)&bsum,   g_bsum);
    cudaGetSymbolAddress((void**)&Bhi,    g_Bhi);
    cudaGetSymbolAddress((void**)&Blo,    g_Blo);

    const int nbN  = (n + 255) / 256;
    const int nbE  = (e + 255) / 256;
    const int nbAg = (n + 7) / 8;
    const int nbT  = (n + 127) / 128;   // 391 tiles

    // ---- CSR build + norms + weight conversion ----
    zero_ints      <<<nbN, 256>>>(outdeg, indeg, n);
    conv_w         <<<(6 * DD * DD + 255) / 256, 256>>>(W0, W1, W2, Wout, Bhi, Blo);
    deg_hist       <<<nbE, 256>>>(src, dst, outdeg, indeg, e);
    scan_block_sums<<<nbN, 256>>>(indeg, bsum, n);
    scan_bsums     <<<1,   256>>>(bsum, nbN);
    scan_final     <<<nbN, 256>>>(indeg, bsum, rowptr, cursor, n, e);
    norms_kernel   <<<nbN, 256>>>(outdeg, indeg, srcn, dstn, n);
    scatter_edges  <<<nbE, 256>>>(src, dst, cursor, colidx, e);

    // ---- layer 1 ----
    agg_kernel<0><<<nbAg, 256>>>(feats, rowptr, colidx, srcn, A, nullptr, n);
    mma_gemm<0, 1><<<nbT, 256>>>(A, nullptr, nullptr,
                                 Bhi + 0 * DD * DD, Blo + 0 * DD * DD,
                                 nullptr, nullptr, nullptr, nullptr,
                                 b0, dstn, h0, n);
    // ---- layer 2 (+ F0) ----
    agg_kernel<1><<<nbAg, 256>>>(h0, rowptr, colidx, srcn, A, F0, n);
    mma_gemm<0, 1><<<nbT, 256>>>(A, nullptr, nullptr,
                                 Bhi + 1 * DD * DD, Blo + 1 * DD * DD,
                                 nullptr, nullptr, nullptr, nullptr,
                                 b1, dstn, h1, n);
    // ---- layer 3 (+ F1); h2 reuses h0 ----
    agg_kernel<1><<<nbAg, 256>>>(h1, rowptr, colidx, srcn, A, F1, n);
    mma_gemm<0, 1><<<nbT, 256>>>(A, nullptr, nullptr,
                                 Bhi + 2 * DD * DD, Blo + 2 * DD * DD,
                                 nullptr, nullptr, nullptr, nullptr,
                                 b2, dstn, h0, n);
    // ---- F2 = plain agg(h2) ----
    agg_kernel<2><<<nbAg, 256>>>(h0, rowptr, colidx, srcn, nullptr, F2, n);
    // ---- out = [F0 F1 F2] @ Wout + bout  (one K=384 GEMM) ----
    mma_gemm<1, 3><<<nbT, 256>>>(F0, F1, F2,
                                 Bhi + 3 * DD * DD, Blo + 3 * DD * DD,
                                 Bhi + 4 * DD * DD, Blo + 4 * DD * DD,
                                 Bhi + 5 * DD * DD, Blo + 5 * DD * DD,
                                 bout, dstn, out, n);
}

// round 7
// speedup vs baseline: 1.2074x; 1.1223x over previous
#include <cuda_runtime.h>
#include <cuda_bf16.h>
#include <mma.h>
#include <cuda_pipeline.h>
#include <cstdint>

using namespace nvcuda;

// ---------------------------------------------------------------------------
// JKNet R7: wmma bf16 hi/lo 3-pass GEMM with full-K single staging.
// 64-row tiles, dynamic smem 110KB (2 blocks/SM), cp.async B staging,
// one __syncthreads per K-segment. No inline PTX anywhere (R6 lesson).
// ---------------------------------------------------------------------------

#define NN 50000
#define EE 800000
#define DD 128

// ---------------- scratch ---------------------------------------------------
__device__ float g_h0[NN * DD];
__device__ float g_h1[NN * DD];
__device__ float g_A [NN * DD];
__device__ float g_F0[NN * DD];
__device__ float g_F1[NN * DD];
__device__ float g_F2[NN * DD];
__device__ float g_srcn[NN];
__device__ float g_dstn[NN];
__device__ int   g_outdeg[NN];
__device__ int   g_indeg [NN];
__device__ int   g_rowptr[NN + 1];
__device__ int   g_cursor[NN];
__device__ int   g_colidx[EE];
__device__ int   g_bsum[256];
__device__ __nv_bfloat16 g_Bhi[6 * DD * DD];
__device__ __nv_bfloat16 g_Blo[6 * DD * DD];

// ---------------- CSR build -------------------------------------------------
__global__ void zero_ints(int* __restrict__ a, int* __restrict__ b, int n) {
    int i = blockIdx.x * blockDim.x + threadIdx.x;
    if (i < n) { a[i] = 0; b[i] = 0; }
}
__global__ void deg_hist(const int* __restrict__ src, const int* __restrict__ dst,
                         int* __restrict__ outdeg, int* __restrict__ indeg, int e) {
    int i = blockIdx.x * blockDim.x + threadIdx.x;
    if (i < e) { atomicAdd(&outdeg[src[i]], 1); atomicAdd(&indeg[dst[i]], 1); }
}
__global__ void scan_block_sums(const int* __restrict__ deg, int* __restrict__ bsum, int n) {
    __shared__ int s[256];
    int i = blockIdx.x * 256 + threadIdx.x;
    s[threadIdx.x] = (i < n) ? deg[i] : 0;
    __syncthreads();
    for (int off = 128; off > 0; off >>= 1) {
        if (threadIdx.x < off) s[threadIdx.x] += s[threadIdx.x + off];
        __syncthreads();
    }
    if (threadIdx.x == 0) bsum[blockIdx.x] = s[0];
}
__global__ void scan_bsums(int* __restrict__ bsum, int nb) {
    __shared__ int s[256];
    int t = threadIdx.x;
    int v = (t < nb) ? bsum[t] : 0;
    s[t] = v;
    __syncthreads();
    for (int off = 1; off < 256; off <<= 1) {
        int add = (t >= off) ? s[t - off] : 0;
        __syncthreads();
        s[t] += add;
        __syncthreads();
    }
    if (t < nb) bsum[t] = s[t] - v;
}
// scan_final + norms fused
__global__ void scan_final(const int* __restrict__ deg, const int* __restrict__ bsum,
                           const int* __restrict__ outdeg,
                           int* __restrict__ rowptr, int* __restrict__ cursor,
                           float* __restrict__ sn, float* __restrict__ dn,
                           int n, int etot) {
    __shared__ int s[256];
    int t = threadIdx.x;
    int i = blockIdx.x * 256 + t;
    int v = (i < n) ? deg[i] : 0;
    s[t] = v;
    __syncthreads();
    for (int off = 1; off < 256; off <<= 1) {
        int add = (t >= off) ? s[t - off] : 0;
        __syncthreads();
        s[t] += add;
        __syncthreads();
    }
    int ex = bsum[blockIdx.x] + s[t] - v;
    if (i < n) {
        rowptr[i] = ex;
        cursor[i] = ex;
        sn[i] = rsqrtf((float)max(outdeg[i], 1));
        dn[i] = rsqrtf((float)max(v, 1));
    }
    if (i == 0) rowptr[n] = etot;
}
__global__ void scatter_edges(const int* __restrict__ src, const int* __restrict__ dst,
                              int* __restrict__ cursor, int* __restrict__ colidx, int e) {
    int i = blockIdx.x * blockDim.x + threadIdx.x;
    if (i < e) {
        int p = atomicAdd(&cursor[dst[i]], 1);
        colidx[p] = src[i];
    }
}

// ---------------- W conversion: fp32 -> bf16 hi/lo, row-major [k][n] --------
__global__ void conv_w(const float* __restrict__ W0, const float* __restrict__ W1,
                       const float* __restrict__ W2, const float* __restrict__ Wout,
                       __nv_bfloat16* __restrict__ hi, __nv_bfloat16* __restrict__ lo) {
    int idx = blockIdx.x * blockDim.x + threadIdx.x;
    if (idx >= 6 * DD * DD) return;
    int m = idx / (DD * DD);
    int rem = idx % (DD * DD);
    const float* src = (m == 0) ? W0 : (m == 1) ? W1 : (m == 2) ? W2
                                     : (Wout + (m - 3) * DD * DD);
    float v = src[rem];
    __nv_bfloat16 h = __float2bfloat16(v);
    __nv_bfloat16 l = __float2bfloat16(v - __bfloat162float(h));
    hi[idx] = h;
    lo[idx] = l;
}

// ---------------- sparse aggregation (gather, warp per node) ----------------
template <int MODE>   // 0 scaled, 1 dual, 2 plain
__global__ void agg_kernel(const float* __restrict__ X,
                           const int* __restrict__ rowptr,
                           const int* __restrict__ colidx,
                           const float* __restrict__ srcn,
                           float* __restrict__ outS,
                           float* __restrict__ outP, int n) {
    int warp = (blockIdx.x * blockDim.x + threadIdx.x) >> 5;
    int lane = threadIdx.x & 31;
    if (warp >= n) return;
    int beg = rowptr[warp];
    int end = rowptr[warp + 1];
    const float4* __restrict__ X4 = (const float4*)X;

    float4 aS = make_float4(0.f, 0.f, 0.f, 0.f);
    float4 aP = make_float4(0.f, 0.f, 0.f, 0.f);
    int e = beg;
    for (; e + 3 < end; e += 4) {
        int s0 = colidx[e], s1 = colidx[e + 1];
        int s2 = colidx[e + 2], s3 = colidx[e + 3];
        float4 v0 = X4[s0 * 32 + lane];
        float4 v1 = X4[s1 * 32 + lane];
        float4 v2 = X4[s2 * 32 + lane];
        float4 v3 = X4[s3 * 32 + lane];
        if (MODE != 2) {
            float n0 = srcn[s0], n1 = srcn[s1], n2 = srcn[s2], n3 = srcn[s3];
            aS.x += v0.x * n0 + v1.x * n1 + v2.x * n2 + v3.x * n3;
            aS.y += v0.y * n0 + v1.y * n1 + v2.y * n2 + v3.y * n3;
            aS.z += v0.z * n0 + v1.z * n1 + v2.z * n2 + v3.z * n3;
            aS.w += v0.w * n0 + v1.w * n1 + v2.w * n2 + v3.w * n3;
        }
        if (MODE != 0) {
            aP.x += v0.x + v1.x + v2.x + v3.x;
            aP.y += v0.y + v1.y + v2.y + v3.y;
            aP.z += v0.z + v1.z + v2.z + v3.z;
            aP.w += v0.w + v1.w + v2.w + v3.w;
        }
    }
    for (; e < end; e++) {
        int s0 = colidx[e];
        float4 v0 = X4[s0 * 32 + lane];
        if (MODE != 2) {
            float n0 = srcn[s0];
            aS.x += v0.x * n0; aS.y += v0.y * n0; aS.z += v0.z * n0; aS.w += v0.w * n0;
        }
        if (MODE != 0) { aP.x += v0.x; aP.y += v0.y; aP.z += v0.z; aP.w += v0.w; }
    }
    if (MODE != 2) ((float4*)outS)[warp * 32 + lane] = aS;
    if (MODE != 0) ((float4*)outP)[warp * 32 + lane] = aP;
}

// ---------------- WMMA GEMM, 64-row tiles, full-K staging -------------------
// Dynamic smem layout (bytes):
//   sAhi [64 x 136 bf16]  @ 0        (17408)
//   sAlo                  @ 17408
//   sBhi [128 x 136 bf16] @ 34816    (34816)
//   sBlo                  @ 69632
//   sBias [8][16][16] f32 @ 104448   (8192)
// total 112640 -> 2 blocks/SM.
#define ALD 136
#define BLD 136
#define SM_AHI 0
#define SM_ALO 17408
#define SM_BHI 34816
#define SM_BLO 69632
#define SM_BIAS 104448
#define SM_TOT 112640

// MODE 0: C = relu((A*dn)@W + bias);  MODE 1: C = A@W + bias.
template <int MODE, int NSEG>
__global__ void __launch_bounds__(256, 2)
mma_gemm(const float* __restrict__ A0, const float* __restrict__ A1,
         const float* __restrict__ A2,
         const __nv_bfloat16* __restrict__ B0h, const __nv_bfloat16* __restrict__ B0l,
         const __nv_bfloat16* __restrict__ B1h, const __nv_bfloat16* __restrict__ B1l,
         const __nv_bfloat16* __restrict__ B2h, const __nv_bfloat16* __restrict__ B2l,
         const float* __restrict__ bias, const float* __restrict__ dstn,
         float* __restrict__ C, int n) {
    extern __shared__ unsigned char smem[];
    __nv_bfloat16* sAhi = (__nv_bfloat16*)(smem + SM_AHI);
    __nv_bfloat16* sAlo = (__nv_bfloat16*)(smem + SM_ALO);
    __nv_bfloat16* sBhi = (__nv_bfloat16*)(smem + SM_BHI);
    __nv_bfloat16* sBlo = (__nv_bfloat16*)(smem + SM_BLO);
    float*         sBias = (float*)(smem + SM_BIAS);

    const int tid  = threadIdx.x;
    const int wid  = tid >> 5;
    const int row0 = blockIdx.x * 64;

    const float* As[3]          = {A0, A1, A2};
    const __nv_bfloat16* Bhs[3] = {B0h, B1h, B2h};
    const __nv_bfloat16* Bls[3] = {B0l, B1l, B2l};

    // replicated bias tiles: sBias[nt*256 + r*16 + c] = bias[nt*16+c]
    for (int idx = tid; idx < 2048; idx += 256) {
        int nt = idx >> 8;
        int c  = idx & 15;
        sBias[idx] = bias[nt * 16 + c];
    }
    __syncthreads();

    const int rt = wid >> 1;          // row-tile 0..3 (rows rt*16..+15)
    const int ch = wid & 1;           // col half: n-tiles ch*4..ch*4+3

    wmma::fragment<wmma::accumulator, 16, 16, 16, float> acc[4];
#pragma unroll
    for (int j = 0; j < 4; j++)
        wmma::load_matrix_sync(acc[j], sBias + (ch * 4 + j) * 256, 16, wmma::mem_row_major);

#pragma unroll
    for (int seg = 0; seg < NSEG; seg++) {
        if (seg > 0) __syncthreads();   // protect smem from previous compute
        // --- async-copy full B (hi+lo): 2048 uint4 each ---
        {
            const __nv_bfloat16* Bh = Bhs[seg];
            const __nv_bfloat16* Bl = Bls[seg];
#pragma unroll
            for (int i = 0; i < 8; i++) {
                int idx = i * 256 + tid;          // 0..2047
                int r   = idx >> 4;               // 16 uint4 per 128-col row
                int c16 = idx & 15;
                __pipeline_memcpy_async(sBhi + r * BLD + c16 * 8, Bh + r * 128 + c16 * 8, 16);
                __pipeline_memcpy_async(sBlo + r * BLD + c16 * 8, Bl + r * 128 + c16 * 8, 16);
            }
            __pipeline_commit();
        }
        // --- stage A [64 x 128] fp32 -> (A*dn) bf16 hi/lo (overlaps cp.async) ---
        {
            const float* Ap = As[seg];
#pragma unroll
            for (int i = 0; i < 8; i++) {
                int idx4 = i * 256 + tid;         // 0..2047 float4
                int row  = idx4 >> 5;             // 32 float4 per 128-col row
                int c4   = idx4 & 31;
                float4 v = make_float4(0.f, 0.f, 0.f, 0.f);
                float dn = 1.f;
                if (row0 + row < n) {
                    v = *(const float4*)(Ap + (size_t)(row0 + row) * 128 + c4 * 4);
                    if (MODE == 0) dn = dstn[row0 + row];
                }
                if (MODE == 0) { v.x *= dn; v.y *= dn; v.z *= dn; v.w *= dn; }
                __nv_bfloat16 h0 = __float2bfloat16(v.x);
                __nv_bfloat16 h1 = __float2bfloat16(v.y);
                __nv_bfloat16 h2 = __float2bfloat16(v.z);
                __nv_bfloat16 h3 = __float2bfloat16(v.w);
                __nv_bfloat16 l0 = __float2bfloat16(v.x - __bfloat162float(h0));
                __nv_bfloat16 l1 = __float2bfloat16(v.y - __bfloat162float(h1));
                __nv_bfloat16 l2 = __float2bfloat16(v.z - __bfloat162float(h2));
                __nv_bfloat16 l3 = __float2bfloat16(v.w - __bfloat162float(h3));
                __nv_bfloat16* dh = sAhi + row * ALD + c4 * 4;
                __nv_bfloat16* dl = sAlo + row * ALD + c4 * 4;
                dh[0] = h0; dh[1] = h1; dh[2] = h2; dh[3] = h3;
                dl[0] = l0; dl[1] = l1; dl[2] = l2; dl[3] = l3;
            }
        }
        __pipeline_wait_prior(0);
        __syncthreads();

        // --- compute: full K in one pass, 8 k-steps ---
#pragma unroll
        for (int kk = 0; kk < 8; kk++) {
            wmma::fragment<wmma::matrix_a, 16, 16, 16, __nv_bfloat16, wmma::row_major> ah, al;
            wmma::load_matrix_sync(ah, sAhi + (rt * 16) * ALD + kk * 16, ALD);
            wmma::load_matrix_sync(al, sAlo + (rt * 16) * ALD + kk * 16, ALD);
#pragma unroll
            for (int j = 0; j < 4; j++) {
                int nt = ch * 4 + j;
                wmma::fragment<wmma::matrix_b, 16, 16, 16, __nv_bfloat16, wmma::row_major> bh, bl;
                wmma::load_matrix_sync(bh, sBhi + (kk * 16) * BLD + nt * 16, BLD);
                wmma::load_matrix_sync(bl, sBlo + (kk * 16) * BLD + nt * 16, BLD);
                wmma::mma_sync(acc[j], ah, bh, acc[j]);
                wmma::mma_sync(acc[j], ah, bl, acc[j]);
                wmma::mma_sync(acc[j], al, bh, acc[j]);
            }
        }
    }

    // --- epilogue: relu on fragments, direct store (16-row tiles all-or-none) ---
    if (row0 + rt * 16 + 16 <= n) {
#pragma unroll
        for (int j = 0; j < 4; j++) {
            if (MODE == 0) {
#pragma unroll
                for (int i = 0; i < acc[j].num_elements; i++)
                    acc[j].x[i] = fmaxf(acc[j].x[i], 0.f);
            }
            wmma::store_matrix_sync(C + (size_t)(row0 + rt * 16) * 128 + (ch * 4 + j) * 16,
                                    acc[j], 128, wmma::mem_row_major);
        }
    }
}

// ---------------------------------------------------------------------------
extern "C" void kernel_launch(void* const* d_in, const int* in_sizes, int n_in,
                              void* d_out, int out_size) {
    const float* feats = (const float*)d_in[0];
    const int*   src   = (const int*)  d_in[1];
    const int*   dst   = (const int*)  d_in[2];
    const float* W0    = (const float*)d_in[3];
    const float* b0    = (const float*)d_in[4];
    const float* W1    = (const float*)d_in[5];
    const float* b1    = (const float*)d_in[6];
    const float* W2    = (const float*)d_in[7];
    const float* b2    = (const float*)d_in[8];
    const float* Wout  = (const float*)d_in[9];
    const float* bout  = (const float*)d_in[10];
    float*       out   = (float*)d_out;

    const int n = in_sizes[0] / DD;
    const int e = in_sizes[1];

    float *A, *F0, *F1, *F2, *h0, *h1, *srcn, *dstn;
    int *outdeg, *indeg, *rowptr, *cursor, *colidx, *bsum;
    __nv_bfloat16 *Bhi, *Blo;
    cudaGetSymbolAddress((void**)&A,      g_A);
    cudaGetSymbolAddress((void**)&F0,     g_F0);
    cudaGetSymbolAddress((void**)&F1,     g_F1);
    cudaGetSymbolAddress((void**)&F2,     g_F2);
    cudaGetSymbolAddress((void**)&h0,     g_h0);
    cudaGetSymbolAddress((void**)&h1,     g_h1);
    cudaGetSymbolAddress((void**)&srcn,   g_srcn);
    cudaGetSymbolAddress((void**)&dstn,   g_dstn);
    cudaGetSymbolAddress((void**)&outdeg, g_outdeg);
    cudaGetSymbolAddress((void**)&indeg,  g_indeg);
    cudaGetSymbolAddress((void**)&rowptr, g_rowptr);
    cudaGetSymbolAddress((void**)&cursor, g_cursor);
    cudaGetSymbolAddress((void**)&colidx, g_colidx);
    cudaGetSymbolAddress((void**)&bsum,   g_bsum);
    cudaGetSymbolAddress((void**)&Bhi,    g_Bhi);
    cudaGetSymbolAddress((void**)&Blo,    g_Blo);

    const int nbN  = (n + 255) / 256;
    const int nbE  = (e + 255) / 256;
    const int nbAg = (n + 7) / 8;
    const int nbT  = (n + 63) / 64;     // 782 tiles

    cudaFuncSetAttribute(mma_gemm<0, 1>, cudaFuncAttributeMaxDynamicSharedMemorySize, SM_TOT);
    cudaFuncSetAttribute(mma_gemm<1, 3>, cudaFuncAttributeMaxDynamicSharedMemorySize, SM_TOT);

    // ---- CSR build + norms + weight conversion ----
    zero_ints      <<<nbN, 256>>>(outdeg, indeg, n);
    conv_w         <<<(6 * DD * DD + 255) / 256, 256>>>(W0, W1, W2, Wout, Bhi, Blo);
    deg_hist       <<<nbE, 256>>>(src, dst, outdeg, indeg, e);
    scan_block_sums<<<nbN, 256>>>(indeg, bsum, n);
    scan_bsums     <<<1,   256>>>(bsum, nbN);
    scan_final     <<<nbN, 256>>>(indeg, bsum, outdeg, rowptr, cursor, srcn, dstn, n, e);
    scatter_edges  <<<nbE, 256>>>(src, dst, cursor, colidx, e);

    // ---- layer 1 ----
    agg_kernel<0><<<nbAg, 256>>>(feats, rowptr, colidx, srcn, A, nullptr, n);
    mma_gemm<0, 1><<<nbT, 256, SM_TOT>>>(A, nullptr, nullptr,
                                         Bhi + 0 * DD * DD, Blo + 0 * DD * DD,
                                         nullptr, nullptr, nullptr, nullptr,
                                         b0, dstn, h0, n);
    // ---- layer 2 (+ F0) ----
    agg_kernel<1><<<nbAg, 256>>>(h0, rowptr, colidx, srcn, A, F0, n);
    mma_gemm<0, 1><<<nbT, 256, SM_TOT>>>(A, nullptr, nullptr,
                                         Bhi + 1 * DD * DD, Blo + 1 * DD * DD,
                                         nullptr, nullptr, nullptr, nullptr,
                                         b1, dstn, h1, n);
    // ---- layer 3 (+ F1); h2 reuses h0 ----
    agg_kernel<1><<<nbAg, 256>>>(h1, rowptr, colidx, srcn, A, F1, n);
    mma_gemm<0, 1><<<nbT, 256, SM_TOT>>>(A, nullptr, nullptr,
                                         Bhi + 2 * DD * DD, Blo + 2 * DD * DD,
                                         nullptr, nullptr, nullptr, nullptr,
                                         b2, dstn, h0, n);
    // ---- F2 = plain agg(h2) ----
    agg_kernel<2><<<nbAg, 256>>>(h0, rowptr, colidx, srcn, nullptr, F2, n);
    // ---- out = [F0 F1 F2] @ Wout + bout  (one K=384 GEMM) ----
    mma_gemm<1, 3><<<nbT, 256, SM_TOT>>>(F0, F1, F2,
                                         Bhi + 3 * DD * DD, Blo + 3 * DD * DD,
                                         Bhi + 4 * DD * DD, Blo + 4 * DD * DD,
                                         Bhi + 5 * DD * DD, Blo + 5 * DD * DD,
                                         bout, dstn, out, n);
}